// round 13
// baseline (speedup 1.0000x reference)
#include <cuda_runtime.h>
#include <stdint.h>

// Fused projection + greedy per-pixel NMS. Output dtype is FLOAT32.
//   coords_grid: [N, M, 3, H, W] f32,  anchor_P: [N, 3, 4] f32
//   out: [N, H, W, 8] f32 (indices as floats)
//
// R13: 2 pixels/thread, 128-thread CTAs. Fixes both residual structural
// limits: wave quantization (1200/740=1.62 waves -> 1200/1036=1.16) and
// single-chain ILP (two independent NMS chains interleave per warp).
// R7's 2-px attempt died at 94 regs/22.8% occ; state is now ~25 regs/px
// (byte-packed indices, uniform-promoted P), so (128,7) holds ~43.8% occ.
#define TOPK 8

__device__ __forceinline__ float fast_rcp(float z) {
    float r;
    asm("rcp.approx.ftz.f32 %0, %1;" : "=f"(r) : "f"(z));
    return r;
}

#define PROJECT(cx, cy, cz, X, Y)                                             \
  do {                                                                        \
    const float X0 = fmaf(p00, (cx), fmaf(p01, (cy), fmaf(p02, (cz), p03)));  \
    const float X1 = fmaf(p10, (cx), fmaf(p11, (cy), fmaf(p12, (cz), p13)));  \
    const float X2 = fmaf(p20, (cx), fmaf(p21, (cy), fmaf(p22, (cz), p23)));  \
    const float zc = fmaxf(X2, 1e-6f);                                        \
    const float iv = fast_rcp(zc);                                            \
    (X) = X0 * iv;                                                            \
    (Y) = X1 * iv;                                                            \
  } while (0)

// One pipelined candidate step for pixel stream P_ (0 or 1):
// prefetch coords(m+2), project(m+1), suppress/insert(m).
#define CAND_P(P_, MVAL)                                                      \
  do {                                                                        \
    const int o = (P_) * 128;                                                 \
    const float nx = q[o];                                                    \
    const float ny = q[o + plane];                                            \
    const float nz = q[o + 2 * plane];                                        \
    float x2, y2;                                                             \
    PROJECT(cx1[P_], cy1[P_], cz1[P_], x2, y2);                               \
    float d2_[TOPK];                                                          \
    _Pragma("unroll")                                                         \
    for (int k = 0; k < TOPK; k++) {                                          \
      const float dx = sx[P_][k] - x1[P_];                                    \
      const float dy = sy[P_][k] - y1[P_];                                    \
      d2_[k] = fmaf(dx, dx, dy * dy);                                         \
    }                                                                         \
    const float dmn = fminf(fminf(fminf(d2_[0], d2_[1]), fminf(d2_[2], d2_[3])), \
                            fminf(fminf(d2_[4], d2_[5]), fminf(d2_[6], d2_[7]))); \
    if ((dmn > 4.0f) && (cnt[P_] < TOPK)) {                                   \
      _Pragma("unroll")                                                       \
      for (int k = 1; k < TOPK; k++) {                                        \
        if (cnt[P_] == k) { sx[P_][k] = x1[P_]; sy[P_][k] = y1[P_]; }         \
      }                                                                       \
      si64[P_] |= (uint64_t)(uint32_t)(MVAL) << (cnt[P_] * 8);                \
      cnt[P_]++;                                                              \
    }                                                                         \
    x1[P_] = x2; y1[P_] = y2;                                                 \
    cx1[P_] = nx; cy1[P_] = ny; cz1[P_] = nz;                                 \
  } while (0)

// Fast path: HW % 256 == 0 (CTA's 256-pixel span lies in one image),
// 2 <= M <= 255. 128 threads x 2 pixels (t and t+128).
template <bool VEC_STORE>
__global__ __launch_bounds__(128, 7)
void nms_coords_kernel2(const float* __restrict__ coords,
                        const float* __restrict__ P,
                        float* __restrict__ out,
                        int HW, int M)
{
    const int bpix = blockIdx.x * 256;           // global pixel base of CTA
    const int n    = bpix / HW;                  // block-uniform image index
    const int lpix = bpix - n * HW + threadIdx.x;

    const float* Pn = P + n * 12;
    const float p00 = Pn[0], p01 = Pn[1], p02 = Pn[2],  p03 = Pn[3];
    const float p10 = Pn[4], p11 = Pn[5], p12 = Pn[6],  p13 = Pn[7];
    const float p20 = Pn[8], p21 = Pn[9], p22 = Pn[10], p23 = Pn[11];

    const long long plane   = HW;
    const long long mstride = 3 * plane;
    // base of pixel stream 0; stream 1 offsets all loads by +128 floats
    const float* base  = coords + (long long)n * M * mstride + lpix;
    const float* lastp = base + (long long)(M - 1) * mstride;

    float sx[2][TOPK], sy[2][TOPK];
#pragma unroll
    for (int p = 0; p < 2; p++)
#pragma unroll
        for (int k = 0; k < TOPK; k++) { sx[p][k] = 1e9f; sy[p][k] = 1e9f; }
    uint64_t si64[2] = {0, 0};      // byte-packed kept indices (M < 256)
    int cnt[2];

    // Peel m = 0: always kept (sentinel slots, cnt==0); index byte stays 0.
#pragma unroll
    for (int p = 0; p < 2; p++) {
        const int o = p * 128;
        const float cx = base[o];
        const float cy = base[o + plane];
        const float cz = base[o + 2 * plane];
        PROJECT(cx, cy, cz, sx[p][0], sy[p][0]);
        cnt[p] = 1;
    }

    // Pipeline prime: project m=1, hold coords of m=2, prefetch from m=3.
    const float* s1 = (base + mstride)     < lastp ? (base + mstride)     : lastp;
    const float* s2 = (base + 2 * mstride) < lastp ? (base + 2 * mstride) : lastp;
    float x1[2], y1[2], cx1[2], cy1[2], cz1[2];
#pragma unroll
    for (int p = 0; p < 2; p++) {
        const int o = p * 128;
        const float cx = s1[o], cy = s1[o + plane], cz = s1[o + 2 * plane];
        PROJECT(cx, cy, cz, x1[p], y1[p]);
        cx1[p] = s2[o]; cy1[p] = s2[o + plane]; cz1[p] = s2[o + 2 * plane];
    }
    const float* pf = base + 3 * mstride;

    // Vote-free warm-up: cnt cannot reach 8 before m = 7.
    int m = 1;
    const int mchk = (M < TOPK) ? M : TOPK;
    for (; m < mchk; m++) {
        const float* q = pf < lastp ? pf : lastp;
        CAND_P(0, m);
        CAND_P(1, m);
        pf += mstride;
    }
    // Checked region: exit when every lane finished BOTH pixel streams.
    for (; m < M; m++) {
        const float* q = pf < lastp ? pf : lastp;
        CAND_P(0, m);
        CAND_P(1, m);
        pf += mstride;
        if (__all_sync(0xffffffffu, (cnt[0] >= TOPK) & (cnt[1] >= TOPK))) break;
    }

    // Unpack byte-packed indices and store (pixel p at global bpix+t+p*128).
#pragma unroll
    for (int p = 0; p < 2; p++) {
        const uint32_t lo = (uint32_t)si64[p];
        const uint32_t hi = (uint32_t)(si64[p] >> 32);
        const float f0 = (float)( lo        & 0xff);
        const float f1 = (float)((lo >>  8) & 0xff);
        const float f2 = (float)((lo >> 16) & 0xff);
        const float f3 = (float)((lo >> 24)       );
        const float f4 = (float)( hi        & 0xff);
        const float f5 = (float)((hi >>  8) & 0xff);
        const float f6 = (float)((hi >> 16) & 0xff);
        const float f7 = (float)((hi >> 24)       );
        const long long opix = (long long)bpix + threadIdx.x + p * 128;
        if (VEC_STORE) {
            float4* o = reinterpret_cast<float4*>(out) + opix * 2;
            o[0] = make_float4(f0, f1, f2, f3);
            o[1] = make_float4(f4, f5, f6, f7);
        } else {
            float* o = out + opix * TOPK;
            o[0]=f0; o[1]=f1; o[2]=f2; o[3]=f3; o[4]=f4; o[5]=f5; o[6]=f6; o[7]=f7;
        }
    }
}

// Generic fallback (any M, any HW alignment): simple, correct.
__global__ __launch_bounds__(256)
void nms_coords_kernel_generic(const float* __restrict__ coords,
                               const float* __restrict__ P,
                               float* __restrict__ out,
                               int HW, int M, int total)
{
    const int tid = blockIdx.x * 256 + threadIdx.x;
    if (tid >= total) return;
    const int n   = tid / HW;
    const int pix = tid - n * HW;
    const float* Pn = P + n * 12;
    const float p00 = Pn[0], p01 = Pn[1], p02 = Pn[2],  p03 = Pn[3];
    const float p10 = Pn[4], p11 = Pn[5], p12 = Pn[6],  p13 = Pn[7];
    const float p20 = Pn[8], p21 = Pn[9], p22 = Pn[10], p23 = Pn[11];
    const long long plane = HW, mstride = 3 * plane;
    const float* cm = coords + (long long)n * M * mstride + pix;

    float sx[TOPK], sy[TOPK]; int si[TOPK];
#pragma unroll
    for (int k = 0; k < TOPK; k++) { sx[k] = 1e9f; sy[k] = 1e9f; si[k] = 0; }
    int cnt = 0;
    for (int m = 0; m < M; m++, cm += mstride) {
        const float cx = cm[0], cy = cm[plane], cz = cm[2 * plane];
        const float X0 = fmaf(p00, cx, fmaf(p01, cy, fmaf(p02, cz, p03)));
        const float X1 = fmaf(p10, cx, fmaf(p11, cy, fmaf(p12, cz, p13)));
        const float X2 = fmaf(p20, cx, fmaf(p21, cy, fmaf(p22, cz, p23)));
        const float zc = fmaxf(X2, 1e-6f);
        const float x = X0 / zc, y = X1 / zc;
        float dmin = 3.402823e38f;
#pragma unroll
        for (int k = 0; k < TOPK; k++) {
            const float dx = sx[k] - x, dy = sy[k] - y;
            dmin = fminf(dmin, fmaf(dx, dx, dy * dy));
        }
        if (dmin > 4.0f && cnt < TOPK) {
#pragma unroll
            for (int k = 0; k < TOPK; k++)
                if (cnt == k) { sx[k] = x; sy[k] = y; si[k] = m; }
            cnt++;
        }
    }
    float* o = out + (long long)tid * TOPK;
#pragma unroll
    for (int k = 0; k < TOPK; k++) o[k] = (float)si[k];
}

extern "C" void kernel_launch(void* const* d_in, const int* in_sizes, int n_in,
                              void* d_out, int out_size)
{
    int ci = 0, pi = 0;
    for (int i = 1; i < n_in; i++) {
        if (in_sizes[i] > in_sizes[ci]) ci = i;
        if (in_sizes[i] < in_sizes[pi]) pi = i;
    }
    const float* coords = (const float*)d_in[ci];
    const float* P      = (const float*)d_in[pi];
    float* out          = (float*)d_out;

    const long long p_elems      = in_sizes[pi];
    const long long coords_elems = in_sizes[ci];
    const int N  = (int)(p_elems / 12);
    const int HW = (int)(out_size / (TOPK * (long long)N));
    const int M  = (int)(coords_elems / (3LL * N * HW));
    const int total = N * HW;

    const bool fast = (HW % 256 == 0) && (M >= 2) && (M <= 255);
    if (fast) {
        const int blocks = total / 256;            // 256 pixels per CTA
        if ((((uintptr_t)d_out) & 15u) == 0)
            nms_coords_kernel2<true><<<blocks, 128>>>(coords, P, out, HW, M);
        else
            nms_coords_kernel2<false><<<blocks, 128>>>(coords, P, out, HW, M);
    } else {
        const int blocks = (total + 255) / 256;
        nms_coords_kernel_generic<<<blocks, 256>>>(coords, P, out, HW, M, total);
    }
}

// round 14
// speedup vs baseline: 1.0648x; 1.0648x over previous
#include <cuda_runtime.h>
#include <stdint.h>

// Fused projection + greedy per-pixel NMS. Output dtype is FLOAT32.
//   coords_grid: [N, M, 3, H, W] f32,  anchor_P: [N, 3, 4] f32
//   out: [N, H, W, 8] f32 (indices as floats)
//
// R14: instruction-count attack on the R12 baseline (R13's 2px/thread killed:
// 72 regs -> 32% occ + local-mem spill traffic).
//  * Warm-up specialization: candidate m (m<8) tests only the m occupied
//    slots and selects insert position among k<=m  (56->28 slot tests,
//    49->28 insert selects per pixel).
//  * Vote BEFORE the candidate body in the checked region: warps fully done
//    at m=8 (most of them) skip the wasted body.
#define TOPK 8

__device__ __forceinline__ float fast_rcp(float z) {
    float r;
    asm("rcp.approx.ftz.f32 %0, %1;" : "=f"(r) : "f"(z));
    return r;
}

#define PROJECT(cx, cy, cz, X, Y)                                             \
  do {                                                                        \
    const float X0 = fmaf(p00, (cx), fmaf(p01, (cy), fmaf(p02, (cz), p03)));  \
    const float X1 = fmaf(p10, (cx), fmaf(p11, (cy), fmaf(p12, (cz), p13)));  \
    const float X2 = fmaf(p20, (cx), fmaf(p21, (cy), fmaf(p22, (cz), p23)));  \
    const float zc = fmaxf(X2, 1e-6f);                                        \
    const float iv = fast_rcp(zc);                                            \
    (X) = X0 * iv;                                                            \
    (Y) = X1 * iv;                                                            \
  } while (0)

// Min over the first SLOTS squared distances (SLOTS is a compile-time constant).
template <int SLOTS>
__device__ __forceinline__ float dmin_first(const float* sx, const float* sy,
                                            float x, float y) {
    float d2[SLOTS];
#pragma unroll
    for (int k = 0; k < SLOTS; k++) {
        const float dx = sx[k] - x;
        const float dy = sy[k] - y;
        d2[k] = fmaf(dx, dx, dy * dy);
    }
    float r = d2[0];
#pragma unroll
    for (int k = 1; k < SLOTS; k++) r = fminf(r, d2[k]);
    return r;
}

// One pipelined candidate step specialized on the number of occupied slots.
// Prefetch coords(m+2), project(m+1), suppress/insert(m) testing SLOTS slots.
#define CAND_STEP(SLOTS, MVAL, CNT_GUARD)                                     \
  do {                                                                        \
    const float* q = pf < lastp ? pf : lastp;                                 \
    const float nx = q[0];                                                    \
    const float ny = q[plane];                                                \
    const float nz = q[2 * plane];                                            \
    float x2, y2;                                                             \
    PROJECT(cx1, cy1, cz1, x2, y2);                                           \
    const float dmn = dmin_first<SLOTS>(sx, sy, x1, y1);                      \
    if ((dmn > 4.0f) && (CNT_GUARD)) {                                        \
      _Pragma("unroll")                                                       \
      for (int k = 1; k <= (SLOTS); k++) {                                    \
        if (k < TOPK && cnt == k) { sx[k] = x1; sy[k] = y1; }                 \
      }                                                                       \
      si64 |= (uint64_t)(uint32_t)(MVAL) << (cnt * 8);                        \
      cnt++;                                                                  \
    }                                                                         \
    x1 = x2; y1 = y2;                                                         \
    cx1 = nx; cy1 = ny; cz1 = nz;                                             \
    pf += mstride;                                                            \
  } while (0)

// Fast path: HW % 256 == 0 (CTA lies in one image), 8 <= M <= 255.
template <bool VEC_STORE>
__global__ __launch_bounds__(256, 5)
void nms_coords_kernel(const float* __restrict__ coords,
                       const float* __restrict__ P,
                       float* __restrict__ out,
                       int HW, int M)
{
    // Block-uniform image index -> uniform-register promotion.
    const int bpix = blockIdx.x * 256;
    const int n    = bpix / HW;
    const int pix  = bpix - n * HW + threadIdx.x;

    const float* Pn = P + n * 12;
    const float p00 = Pn[0], p01 = Pn[1], p02 = Pn[2],  p03 = Pn[3];
    const float p10 = Pn[4], p11 = Pn[5], p12 = Pn[6],  p13 = Pn[7];
    const float p20 = Pn[8], p21 = Pn[9], p22 = Pn[10], p23 = Pn[11];

    const long long plane   = HW;
    const long long mstride = 3 * plane;
    const float* base  = coords + (long long)n * M * mstride + pix;
    const float* lastp = base + (long long)(M - 1) * mstride;

    float sx[TOPK], sy[TOPK];
#pragma unroll
    for (int k = 0; k < TOPK; k++) { sx[k] = 1e9f; sy[k] = 1e9f; }
    uint64_t si64 = 0;                    // 8 kept indices, byte-packed (M<256)

    // Peel m = 0: always kept; index byte stays 0.
    {
        const float cx = base[0];
        const float cy = base[plane];
        const float cz = base[2 * plane];
        PROJECT(cx, cy, cz, sx[0], sy[0]);
    }
    int cnt = 1;

    // Pipeline prime: project m=1, hold coords of m=2, prefetch from m=3.
    const float* s1 = (base + mstride)     < lastp ? (base + mstride)     : lastp;
    const float* s2 = (base + 2 * mstride) < lastp ? (base + 2 * mstride) : lastp;
    float x1, y1;
    {
        const float cx = s1[0], cy = s1[plane], cz = s1[2 * plane];
        PROJECT(cx, cy, cz, x1, y1);
    }
    float cx1 = s2[0], cy1 = s2[plane], cz1 = s2[2 * plane];
    const float* pf = base + 3 * mstride;

    // Specialized warm-up, m = 1..7: candidate m only faces m occupied slots,
    // and cnt < TOPK is guaranteed (cnt <= m < 8) so the guard is just `true`.
    CAND_STEP(1, 1, true);
    CAND_STEP(2, 2, true);
    CAND_STEP(3, 3, true);
    CAND_STEP(4, 4, true);
    CAND_STEP(5, 5, true);
    CAND_STEP(6, 6, true);
    CAND_STEP(7, 7, true);

    // Checked region: vote FIRST (warps complete at m=8 skip the body).
    for (int m = TOPK; m < M; m++) {
        if (__all_sync(0xffffffffu, cnt >= TOPK)) break;
        CAND_STEP(8, m, cnt < TOPK);
    }

    // Unpack byte-packed indices to floats.
    const uint32_t lo = (uint32_t)si64;
    const uint32_t hi = (uint32_t)(si64 >> 32);
    const float f0 = (float)( lo        & 0xff);
    const float f1 = (float)((lo >>  8) & 0xff);
    const float f2 = (float)((lo >> 16) & 0xff);
    const float f3 = (float)((lo >> 24)       );
    const float f4 = (float)( hi        & 0xff);
    const float f5 = (float)((hi >>  8) & 0xff);
    const float f6 = (float)((hi >> 16) & 0xff);
    const float f7 = (float)((hi >> 24)       );

    const long long opix = (long long)n * HW + pix;
    if (VEC_STORE) {
        float4* o = reinterpret_cast<float4*>(out) + opix * 2;
        o[0] = make_float4(f0, f1, f2, f3);
        o[1] = make_float4(f4, f5, f6, f7);
    } else {
        float* o = out + opix * TOPK;
        o[0]=f0; o[1]=f1; o[2]=f2; o[3]=f3; o[4]=f4; o[5]=f5; o[6]=f6; o[7]=f7;
    }
}

// Generic fallback (any M >= 1, any HW alignment): simple, correct.
__global__ __launch_bounds__(256)
void nms_coords_kernel_generic(const float* __restrict__ coords,
                               const float* __restrict__ P,
                               float* __restrict__ out,
                               int HW, int M, int total)
{
    const int tid = blockIdx.x * 256 + threadIdx.x;
    if (tid >= total) return;
    const int n   = tid / HW;
    const int pix = tid - n * HW;
    const float* Pn = P + n * 12;
    const float p00 = Pn[0], p01 = Pn[1], p02 = Pn[2],  p03 = Pn[3];
    const float p10 = Pn[4], p11 = Pn[5], p12 = Pn[6],  p13 = Pn[7];
    const float p20 = Pn[8], p21 = Pn[9], p22 = Pn[10], p23 = Pn[11];
    const long long plane = HW, mstride = 3 * plane;
    const float* cm = coords + (long long)n * M * mstride + pix;

    float sx[TOPK], sy[TOPK]; int si[TOPK];
#pragma unroll
    for (int k = 0; k < TOPK; k++) { sx[k] = 1e9f; sy[k] = 1e9f; si[k] = 0; }
    int cnt = 0;
    for (int m = 0; m < M; m++, cm += mstride) {
        const float cx = cm[0], cy = cm[plane], cz = cm[2 * plane];
        const float X0 = fmaf(p00, cx, fmaf(p01, cy, fmaf(p02, cz, p03)));
        const float X1 = fmaf(p10, cx, fmaf(p11, cy, fmaf(p12, cz, p13)));
        const float X2 = fmaf(p20, cx, fmaf(p21, cy, fmaf(p22, cz, p23)));
        const float zc = fmaxf(X2, 1e-6f);
        const float x = X0 / zc, y = X1 / zc;
        float dmin = 3.402823e38f;
#pragma unroll
        for (int k = 0; k < TOPK; k++) {
            const float dx = sx[k] - x, dy = sy[k] - y;
            dmin = fminf(dmin, fmaf(dx, dx, dy * dy));
        }
        if (dmin > 4.0f && cnt < TOPK) {
#pragma unroll
            for (int k = 0; k < TOPK; k++)
                if (cnt == k) { sx[k] = x; sy[k] = y; si[k] = m; }
            cnt++;
        }
    }
    float* o = out + (long long)tid * TOPK;
#pragma unroll
    for (int k = 0; k < TOPK; k++) o[k] = (float)si[k];
}

extern "C" void kernel_launch(void* const* d_in, const int* in_sizes, int n_in,
                              void* d_out, int out_size)
{
    int ci = 0, pi = 0;
    for (int i = 1; i < n_in; i++) {
        if (in_sizes[i] > in_sizes[ci]) ci = i;
        if (in_sizes[i] < in_sizes[pi]) pi = i;
    }
    const float* coords = (const float*)d_in[ci];
    const float* P      = (const float*)d_in[pi];
    float* out          = (float*)d_out;

    const long long p_elems      = in_sizes[pi];
    const long long coords_elems = in_sizes[ci];
    const int N  = (int)(p_elems / 12);
    const int HW = (int)(out_size / (TOPK * (long long)N));
    const int M  = (int)(coords_elems / (3LL * N * HW));
    const int total = N * HW;

    const bool fast = (HW % 256 == 0) && (M >= 8) && (M <= 255);
    if (fast) {
        const int blocks = total / 256;            // exact
        if ((((uintptr_t)d_out) & 15u) == 0)
            nms_coords_kernel<true><<<blocks, 256>>>(coords, P, out, HW, M);
        else
            nms_coords_kernel<false><<<blocks, 256>>>(coords, P, out, HW, M);
    } else {
        const int blocks = (total + 255) / 256;
        nms_coords_kernel_generic<<<blocks, 256>>>(coords, P, out, HW, M, total);
    }
}

// round 15
// speedup vs baseline: 1.5270x; 1.4341x over previous
#include <cuda_runtime.h>
#include <stdint.h>

// Fused projection + greedy per-pixel NMS. Output dtype is FLOAT32.
//   coords_grid: [N, M, 3, H, W] f32,  anchor_P: [N, 3, 4] f32
//   out: [N, H, W, 8] f32 (indices as floats)
//
// R15: single-wave push. R12 body (proven 18.9us) compiled into the 8-CTA/SM
// class: __launch_bounds__(256,8) pins 32 regs -> 2048 thr/SM -> the whole
// 307200-thread grid is 1.01 waves (vs 1.62 at 48 regs). To fit, the inner
// loop drops the prefetch clamp (last 2 candidates handled by a no-load
// epilogue that early-exit normally skips).
#define TOPK 8

__device__ __forceinline__ float fast_rcp(float z) {
    float r;
    asm("rcp.approx.ftz.f32 %0, %1;" : "=f"(r) : "f"(z));
    return r;
}

#define PROJECT(cx, cy, cz, X, Y)                                             \
  do {                                                                        \
    const float X0 = fmaf(p00, (cx), fmaf(p01, (cy), fmaf(p02, (cz), p03)));  \
    const float X1 = fmaf(p10, (cx), fmaf(p11, (cy), fmaf(p12, (cz), p13)));  \
    const float X2 = fmaf(p20, (cx), fmaf(p21, (cy), fmaf(p22, (cz), p23)));  \
    const float zc = fmaxf(X2, 1e-6f);                                        \
    const float iv = fast_rcp(zc);                                            \
    (X) = X0 * iv;                                                            \
    (Y) = X1 * iv;                                                            \
  } while (0)

// Suppress/insert candidate m whose projection is in (x1,y1); all 8 slots.
#define SUPPRESS_INSERT(MVAL)                                                 \
  do {                                                                        \
    float d2_[TOPK];                                                          \
    _Pragma("unroll")                                                         \
    for (int k = 0; k < TOPK; k++) {                                          \
      const float dx = sx[k] - x1;                                            \
      const float dy = sy[k] - y1;                                            \
      d2_[k] = fmaf(dx, dx, dy * dy);                                         \
    }                                                                         \
    const float dmn = fminf(fminf(fminf(d2_[0], d2_[1]), fminf(d2_[2], d2_[3])), \
                            fminf(fminf(d2_[4], d2_[5]), fminf(d2_[6], d2_[7]))); \
    if ((dmn > 4.0f) && (cnt < TOPK)) {                                       \
      _Pragma("unroll")                                                       \
      for (int k = 1; k < TOPK; k++) {                                        \
        if (cnt == k) { sx[k] = x1; sy[k] = y1; }                             \
      }                                                                       \
      si64 |= (uint64_t)(uint32_t)(MVAL) << (cnt * 8);                        \
      cnt++;                                                                  \
    }                                                                         \
  } while (0)

// Pipelined step WITHOUT clamp: loads m+2 (caller guarantees m+2 <= M-1),
// projects m+1, suppresses/inserts m.
#define CAND_BODY(MVAL)                                                       \
  do {                                                                        \
    const float nx = pf[0];                                                   \
    const float ny = pf[plane];                                               \
    const float nz = pf[2 * plane];                                           \
    float x2, y2;                                                             \
    PROJECT(cx1, cy1, cz1, x2, y2);                                           \
    SUPPRESS_INSERT(MVAL);                                                    \
    x1 = x2; y1 = y2;                                                         \
    cx1 = nx; cy1 = ny; cz1 = nz;                                             \
    pf += mstride;                                                            \
  } while (0)

// Fast path: HW % 256 == 0 (CTA lies in one image), 10 <= M <= 255.
template <bool VEC_STORE>
__global__ __launch_bounds__(256, 8)   // 32-reg cap -> 2048 thr/SM -> 1 wave
void nms_coords_kernel(const float* __restrict__ coords,
                       const float* __restrict__ P,
                       float* __restrict__ out,
                       int HW, int M)
{
    // Block-uniform image index -> uniform-register promotion.
    const int bpix = blockIdx.x * 256;
    const int n    = bpix / HW;
    const int pix  = bpix - n * HW + threadIdx.x;

    const float* Pn = P + n * 12;
    const float p00 = Pn[0], p01 = Pn[1], p02 = Pn[2],  p03 = Pn[3];
    const float p10 = Pn[4], p11 = Pn[5], p12 = Pn[6],  p13 = Pn[7];
    const float p20 = Pn[8], p21 = Pn[9], p22 = Pn[10], p23 = Pn[11];

    const long long plane   = HW;
    const long long mstride = 3 * plane;
    const float* base = coords + (long long)n * M * mstride + pix;

    float sx[TOPK], sy[TOPK];
#pragma unroll
    for (int k = 0; k < TOPK; k++) { sx[k] = 1e9f; sy[k] = 1e9f; }
    uint64_t si64 = 0;                    // 8 kept indices, byte-packed (M<256)

    // Peel m = 0: always kept; index byte stays 0.
    {
        const float cx = base[0];
        const float cy = base[plane];
        const float cz = base[2 * plane];
        PROJECT(cx, cy, cz, sx[0], sy[0]);
    }
    int cnt = 1;

    // Pipeline prime (M >= 10 so indices 1..3 are all valid, no clamps):
    // project m=1 -> (x1,y1); coords of m=2 in regs; pf points at m=3.
    float x1, y1;
    {
        const float* s1 = base + mstride;
        const float cx = s1[0], cy = s1[plane], cz = s1[2 * plane];
        PROJECT(cx, cy, cz, x1, y1);
    }
    float cx1, cy1, cz1;
    {
        const float* s2 = base + 2 * mstride;
        cx1 = s2[0]; cy1 = s2[plane]; cz1 = s2[2 * plane];
    }
    const float* pf = base + 3 * mstride;

    // Vote-free warm-up m = 1..7 (cnt can't reach 8 yet; m+2 <= 9 <= M-1).
#pragma unroll
    for (int m = 1; m < TOPK; m++) { CAND_BODY(m); }

    // Checked region with prefetch: m = 8 .. M-3 (prefetch m+2 <= M-1).
    bool alldone = false;
    for (int m = TOPK; m <= M - 3; m++) {
        CAND_BODY(m);
        if (__all_sync(0xffffffffu, cnt >= TOPK)) { alldone = true; break; }
    }

    // No-load epilogue for m = M-2, M-1 (skipped when early exit fired).
    if (!alldone) {
        {   // m = M-2: project m=M-1 from held coords, suppress/insert M-2.
            float x2, y2;
            PROJECT(cx1, cy1, cz1, x2, y2);
            SUPPRESS_INSERT(M - 2);
            x1 = x2; y1 = y2;
        }
        {   // m = M-1: suppress/insert only.
            SUPPRESS_INSERT(M - 1);
        }
    }

    // Unpack byte-packed indices to floats.
    const uint32_t lo = (uint32_t)si64;
    const uint32_t hi = (uint32_t)(si64 >> 32);
    const float f0 = (float)( lo        & 0xff);
    const float f1 = (float)((lo >>  8) & 0xff);
    const float f2 = (float)((lo >> 16) & 0xff);
    const float f3 = (float)((lo >> 24)       );
    const float f4 = (float)( hi        & 0xff);
    const float f5 = (float)((hi >>  8) & 0xff);
    const float f6 = (float)((hi >> 16) & 0xff);
    const float f7 = (float)((hi >> 24)       );

    const long long opix = (long long)n * HW + pix;
    if (VEC_STORE) {
        float4* o = reinterpret_cast<float4*>(out) + opix * 2;
        o[0] = make_float4(f0, f1, f2, f3);
        o[1] = make_float4(f4, f5, f6, f7);
    } else {
        float* o = out + opix * TOPK;
        o[0]=f0; o[1]=f1; o[2]=f2; o[3]=f3; o[4]=f4; o[5]=f5; o[6]=f6; o[7]=f7;
    }
}

// Generic fallback (any M >= 1, any HW alignment): simple, correct.
__global__ __launch_bounds__(256)
void nms_coords_kernel_generic(const float* __restrict__ coords,
                               const float* __restrict__ P,
                               float* __restrict__ out,
                               int HW, int M, int total)
{
    const int tid = blockIdx.x * 256 + threadIdx.x;
    if (tid >= total) return;
    const int n   = tid / HW;
    const int pix = tid - n * HW;
    const float* Pn = P + n * 12;
    const float p00 = Pn[0], p01 = Pn[1], p02 = Pn[2],  p03 = Pn[3];
    const float p10 = Pn[4], p11 = Pn[5], p12 = Pn[6],  p13 = Pn[7];
    const float p20 = Pn[8], p21 = Pn[9], p22 = Pn[10], p23 = Pn[11];
    const long long plane = HW, mstride = 3 * plane;
    const float* cm = coords + (long long)n * M * mstride + pix;

    float sx[TOPK], sy[TOPK]; int si[TOPK];
#pragma unroll
    for (int k = 0; k < TOPK; k++) { sx[k] = 1e9f; sy[k] = 1e9f; si[k] = 0; }
    int cnt = 0;
    for (int m = 0; m < M; m++, cm += mstride) {
        const float cx = cm[0], cy = cm[plane], cz = cm[2 * plane];
        const float X0 = fmaf(p00, cx, fmaf(p01, cy, fmaf(p02, cz, p03)));
        const float X1 = fmaf(p10, cx, fmaf(p11, cy, fmaf(p12, cz, p13)));
        const float X2 = fmaf(p20, cx, fmaf(p21, cy, fmaf(p22, cz, p23)));
        const float zc = fmaxf(X2, 1e-6f);
        const float x = X0 / zc, y = X1 / zc;
        float dmin = 3.402823e38f;
#pragma unroll
        for (int k = 0; k < TOPK; k++) {
            const float dx = sx[k] - x, dy = sy[k] - y;
            dmin = fminf(dmin, fmaf(dx, dx, dy * dy));
        }
        if (dmin > 4.0f && cnt < TOPK) {
#pragma unroll
            for (int k = 0; k < TOPK; k++)
                if (cnt == k) { sx[k] = x; sy[k] = y; si[k] = m; }
            cnt++;
        }
    }
    float* o = out + (long long)tid * TOPK;
#pragma unroll
    for (int k = 0; k < TOPK; k++) o[k] = (float)si[k];
}

extern "C" void kernel_launch(void* const* d_in, const int* in_sizes, int n_in,
                              void* d_out, int out_size)
{
    int ci = 0, pi = 0;
    for (int i = 1; i < n_in; i++) {
        if (in_sizes[i] > in_sizes[ci]) ci = i;
        if (in_sizes[i] < in_sizes[pi]) pi = i;
    }
    const float* coords = (const float*)d_in[ci];
    const float* P      = (const float*)d_in[pi];
    float* out          = (float*)d_out;

    const long long p_elems      = in_sizes[pi];
    const long long coords_elems = in_sizes[ci];
    const int N  = (int)(p_elems / 12);
    const int HW = (int)(out_size / (TOPK * (long long)N));
    const int M  = (int)(coords_elems / (3LL * N * HW));
    const int total = N * HW;

    const bool fast = (HW % 256 == 0) && (M >= 10) && (M <= 255);
    if (fast) {
        const int blocks = total / 256;            // exact
        if ((((uintptr_t)d_out) & 15u) == 0)
            nms_coords_kernel<true><<<blocks, 256>>>(coords, P, out, HW, M);
        else
            nms_coords_kernel<false><<<blocks, 256>>>(coords, P, out, HW, M);
    } else {
        const int blocks = (total + 255) / 256;
        nms_coords_kernel_generic<<<blocks, 256>>>(coords, P, out, HW, M, total);
    }
}